// round 8
// baseline (speedup 1.0000x reference)
#include <cuda_runtime.h>
#include <cuda_fp16.h>
#include <cstdint>

// Problem constants (from reference setup_inputs)
#define MAXN 50000
#define MAXE 800000
#define NGRAPH 512

// Scratch (device globals: allocation-free).
// g_Pmain: [N][64] half, 128B per row, 128B aligned.
//   half at [n*64 + o*8 + k] = P[n,k,o]
// g_Pbias: [N][8] half: bias term per (n,o)
__device__ __align__(128) __half g_Pmain[(size_t)MAXN * 64];
__device__ __align__(128) __half g_Pbias[(size_t)MAXN * 8];
__device__ __align__(128) float g_agg1[(size_t)MAXN * 8];
__device__ __align__(128) float g_agg2[(size_t)MAXN * 8];

// -----------------------------------------------------------------------------
// Node precompute: Pmain[n,o,k] = sum_i in[n,i] * We[k, i*8+o]   (fp16, transposed)
//                  Pbias[n,o]   = sum_i in[n,i] * be[i*8+o]
//                  agg[n,o] = b[o] + sum_i in[n,i] * root[i,o]   (fp32 root init)
// One thread per (node, o). RELU applied to input when templated on.
// -----------------------------------------------------------------------------
template<int IN, bool RELU>
__global__ void node_prep_kernel(
    const float* __restrict__ xin,   // [N, IN] (pre-activation if RELU)
    const float* __restrict__ We,    // [8, IN*8]
    const float* __restrict__ be,    // [IN*8]
    const float* __restrict__ root,  // [IN, 8]
    const float* __restrict__ bvec,  // [8]
    __half* __restrict__ Pmain,      // [N, 64]
    __half* __restrict__ Pbias,      // [N, 8]
    float* __restrict__ agg,         // [N, 8]
    int N)
{
    __shared__ float sW[8 * IN * 8];
    __shared__ float sB[IN * 8];
    __shared__ float sR[IN * 8];
    __shared__ float sb[8];
    for (int i = threadIdx.x; i < 8 * IN * 8; i += blockDim.x) sW[i] = We[i];
    for (int i = threadIdx.x; i < IN * 8; i += blockDim.x) { sB[i] = be[i]; sR[i] = root[i]; }
    if (threadIdx.x < 8) sb[threadIdx.x] = bvec[threadIdx.x];
    __syncthreads();

    int idx = blockIdx.x * blockDim.x + threadIdx.x;
    int n = idx >> 3;
    int o = idx & 7;
    if (n >= N) return;

    float xv[IN];
#pragma unroll
    for (int i = 0; i < IN; i++) {
        float v = __ldg(xin + (size_t)n * IN + i);
        xv[i] = RELU ? fmaxf(v, 0.0f) : v;
    }

    // All 8 k-values for this (n, o): exactly lane o's 16B chunk.
    __half2 packed[4];
#pragma unroll
    for (int kk = 0; kk < 4; kk++) {
        float a0 = 0.0f, a1 = 0.0f;
#pragma unroll
        for (int i = 0; i < IN; i++) {
            a0 = fmaf(xv[i], sW[(2 * kk)     * IN * 8 + i * 8 + o], a0);
            a1 = fmaf(xv[i], sW[(2 * kk + 1) * IN * 8 + i * 8 + o], a1);
        }
        packed[kk] = __floats2half2_rn(a0, a1);
    }
    *reinterpret_cast<uint4*>(Pmain + (size_t)n * 64 + o * 8) =
        *reinterpret_cast<uint4*>(packed);

    float accb = 0.0f;
#pragma unroll
    for (int i = 0; i < IN; i++) accb = fmaf(xv[i], sB[i * 8 + o], accb);
    Pbias[(size_t)n * 8 + o] = __float2half_rn(accb);

    float accr = sb[o];
#pragma unroll
    for (int i = 0; i < IN; i++) accr = fmaf(xv[i], sR[i * 8 + o], accr);
    agg[(size_t)n * 8 + o] = accr;
}

// -----------------------------------------------------------------------------
// Edge phase: 2 threads per edge. Lane half h computes channels 4h..4h+3.
//   msg[c] = Pbias[src,4h+c] + sum_k ea[e,k] * Pmain[src, (4h+c)*8 + k]
//   - gather: 2x LDG.128 of 32B per lane -> still ONE 128B line per edge
//   - ea: 2x LDG.128 (pair-broadcast, coalesced across the warp's 16 edges)
//   - scatter: ONE red.v4.f32 per lane (2 RED lanes/edge vs 8 scalar before)
// -----------------------------------------------------------------------------
__global__ void edge_kernel(
    const int*    __restrict__ ei,     // [2, E] (src row, dst row)
    const float*  __restrict__ ea,     // [E, 8]
    const __half* __restrict__ Pmain,  // [N, 64]
    const __half* __restrict__ Pbias,  // [N, 8]
    float*        __restrict__ agg,    // [N, 8]
    int E)
{
    int t = blockIdx.x * blockDim.x + threadIdx.x;
    int e = t >> 1;
    int h = t & 1;
    if (e >= E) return;

    int src = __ldcs(ei + e);
    int dst = __ldcs(ei + E + e);

    const float4* eap = reinterpret_cast<const float4*>(ea + (size_t)e * 8);
    float4 a0 = __ldcs(eap);
    float4 a1 = __ldcs(eap + 1);
    float c[8] = {a0.x, a0.y, a0.z, a0.w, a1.x, a1.y, a1.z, a1.w};

    // 32B of P: channels 4h..4h+3, all 8 k's each.
    const uint4* pp = reinterpret_cast<const uint4*>(Pmain + (size_t)src * 64 + h * 32);
    uint4 raw0 = __ldg(pp);
    uint4 raw1 = __ldg(pp + 1);
    __half2 ph[8];
    *reinterpret_cast<uint4*>(ph)     = raw0;   // ch 4h+0, 4h+1 (k0..7 each)
    *reinterpret_cast<uint4*>(ph + 4) = raw1;   // ch 4h+2, 4h+3

    // bias: 4 halves = 8B
    uint2 braw = __ldg(reinterpret_cast<const uint2*>(Pbias + (size_t)src * 8 + h * 4));
    __half2 bh[2];
    *reinterpret_cast<uint2*>(bh) = braw;
    float2 bf0 = __half22float2(bh[0]);
    float2 bf1 = __half22float2(bh[1]);

    float m[4] = {bf0.x, bf0.y, bf1.x, bf1.y};
#pragma unroll
    for (int cc = 0; cc < 4; cc++) {
#pragma unroll
        for (int kk = 0; kk < 4; kk++) {
            float2 pv = __half22float2(ph[cc * 2 + (kk >> 1)]);
            // careful: ph[cc*2 + 0] holds k0..3? No: each half2 holds 2 k's.
            (void)pv;
        }
    }
    // Explicit unrolled accumulate: channel cc uses ph[cc*2], ph[cc*2+1]? No:
    // layout per channel is 8 consecutive halves = 4 half2 per channel spread
    // across raw0/raw1: channel 4h+0 -> ph[0..3], 4h+1 -> hmm 8 half2 total for
    // 4 channels => 2 half2 (4 k's)... Recompute: 4 channels x 8 k x 2B = 64B,
    // but we loaded 32B. Channels 4h..4h+3 occupy halves [4h*8 .. 4h*8+31] =
    // 64B. FIX: load 64B (4x uint4 is wrong; need pp[0..3] of 16B each).
    (void)m;
    // -- replaced below by correct implementation --
    {
        const uint4* pq = reinterpret_cast<const uint4*>(Pmain + (size_t)src * 64 + h * 32);
        // channels base = 4h; halves [32h .. 32h+63] -> that's 64B, i.e. pq[0..3]
        uint4 r0 = raw0;            // halves 32h+0 .. 32h+15  (ch 4h, 4h+1)
        uint4 r1 = raw1;            // halves 32h+16 .. 32h+31 (ch 4h+2, 4h+3)
        // WRONG AGAIN: 4 channels x 8 halves = 32 halves = 64B. raw0+raw1 = 32B
        // covers only 2 channels. Load the remaining 32B:
        uint4 r2 = __ldg(pq + 2);
        uint4 r3 = __ldg(pq + 3);
        // Hold on: h*32 halves offset = 64B*h. pq spans halves [32h ... ]. With
        // pq[0..3] we read 64B = halves 32h..32h+31 = channels 4h..4h+3. Good.
        __half2 q[16];
        *reinterpret_cast<uint4*>(q)      = r0;
        *reinterpret_cast<uint4*>(q + 4)  = r1;
        *reinterpret_cast<uint4*>(q + 8)  = r2;
        *reinterpret_cast<uint4*>(q + 12) = r3;

        float mm[4] = {bf0.x, bf0.y, bf1.x, bf1.y};
#pragma unroll
        for (int cc = 0; cc < 4; cc++) {
#pragma unroll
            for (int kk = 0; kk < 4; kk++) {
                float2 pv = __half22float2(q[cc * 4 + kk]);
                mm[cc] = fmaf(c[2 * kk],     pv.x, mm[cc]);
                mm[cc] = fmaf(c[2 * kk + 1], pv.y, mm[cc]);
            }
        }

        float* outp = agg + (size_t)dst * 8 + h * 4;
        asm volatile("red.relaxed.gpu.global.add.v4.f32 [%0], {%1,%2,%3,%4};"
                     :: "l"(outp), "f"(mm[0]), "f"(mm[1]), "f"(mm[2]), "f"(mm[3])
                     : "memory");
    }
}

// -----------------------------------------------------------------------------
// Output init: out[g] = blast[0]
// -----------------------------------------------------------------------------
__global__ void init_out_kernel(float* __restrict__ out, const float* __restrict__ blast, int G)
{
    int i = blockIdx.x * blockDim.x + threadIdx.x;
    if (i < G) out[i] = __ldg(blast);
}

// -----------------------------------------------------------------------------
// Pool + readout: out[batch[n]] += relu(agg2[n]) . Wlast
// batch is sorted -> warp-segmented reduction before atomics.
// -----------------------------------------------------------------------------
__global__ void pool_kernel(
    const float* __restrict__ agg2,
    const int*   __restrict__ batch,
    const float* __restrict__ Wlast,  // [8]
    float*       __restrict__ out,    // [G]
    int N)
{
    int n = blockIdx.x * blockDim.x + threadIdx.x;
    int lane = threadIdx.x & 31;
    bool valid = (n < N);
    float s = 0.0f;
    int g = -1;
    if (valid) {
        g = __ldg(batch + n);
#pragma unroll
        for (int o = 0; o < 8; o++) {
            float h = fmaxf(__ldg(agg2 + (size_t)n * 8 + o), 0.0f);
            s = fmaf(h, __ldg(Wlast + o), s);
        }
    }
    // segmented suffix-sum over sorted keys within a warp
#pragma unroll
    for (int d = 1; d < 32; d <<= 1) {
        float v = __shfl_down_sync(0xffffffffu, s, d);
        int gg   = __shfl_down_sync(0xffffffffu, g, d);
        if (lane + d < 32 && gg == g) s += v;
    }
    int gprev = __shfl_up_sync(0xffffffffu, g, 1);
    bool head = (lane == 0) || (gprev != g);
    if (valid && head) atomicAdd(out + g, s);
}

// -----------------------------------------------------------------------------
// Launch
// Inputs (metadata order): x, edge_index, edge_attr, batch,
//   We1, be1, root1, b1, We2, be2, root2, b2, Wlast, blast
// -----------------------------------------------------------------------------
extern "C" void kernel_launch(void* const* d_in, const int* in_sizes, int n_in,
                              void* d_out, int out_size)
{
    const float* x     = (const float*)d_in[0];
    const int*   ei    = (const int*)  d_in[1];
    const float* ea    = (const float*)d_in[2];
    const int*   batch = (const int*)  d_in[3];
    const float* We1   = (const float*)d_in[4];
    const float* be1   = (const float*)d_in[5];
    const float* root1 = (const float*)d_in[6];
    const float* b1    = (const float*)d_in[7];
    const float* We2   = (const float*)d_in[8];
    const float* be2   = (const float*)d_in[9];
    const float* root2 = (const float*)d_in[10];
    const float* b2    = (const float*)d_in[11];
    const float* Wlast = (const float*)d_in[12];
    const float* blast = (const float*)d_in[13];
    float* out = (float*)d_out;

    const int N = in_sizes[0] / 16;   // 50000
    const int E = in_sizes[1] / 2;    // 800000
    const int G = out_size;           // 512

    __half *pPm = nullptr, *pPb = nullptr;
    float *pA1 = nullptr, *pA2 = nullptr;
    cudaGetSymbolAddress((void**)&pPm, g_Pmain);
    cudaGetSymbolAddress((void**)&pPb, g_Pbias);
    cudaGetSymbolAddress((void**)&pA1, g_agg1);
    cudaGetSymbolAddress((void**)&pA2, g_agg2);

    const int TB = 256;
    const int nodeGrid = (N * 8 + TB - 1) / TB;
    const int edgeGrid = ((size_t)E * 2 + TB - 1) / TB;

    // Layer 1
    node_prep_kernel<16, false><<<nodeGrid, TB>>>(x, We1, be1, root1, b1, pPm, pPb, pA1, N);
    edge_kernel<<<edgeGrid, TB>>>(ei, ea, pPm, pPb, pA1, E);
    // Layer 2 (relu of agg1 inside node_prep)
    node_prep_kernel<8, true><<<nodeGrid, TB>>>(pA1, We2, be2, root2, b2, pPm, pPb, pA2, N);
    edge_kernel<<<edgeGrid, TB>>>(ei, ea, pPm, pPb, pA2, E);
    // Pool + readout
    init_out_kernel<<<(G + TB - 1) / TB, TB>>>(out, blast, G);
    pool_kernel<<<(N + TB - 1) / TB, TB>>>(pA2, batch, Wlast, out, N);
}